// round 15
// baseline (speedup 1.0000x reference)
#include <cuda_runtime.h>

#define kB 16
#define kL 1444
#define kD 128
#define kD2 64          // float2 lanes per position
#define kC 21
#define kChunks 76
#define kCL 19          // 76*19 == 1444
#define kT 64
#define kQP 22          // padded Q row stride
#define kWaves 4        // 76 = 4*19 scan waves
#define kTRI 171        // 19*18/2
#define kScanCTAs (kB*kC)          // 336
#define kCopyCTAs (kB*kChunks)     // 1216

typedef unsigned long long ull;

// Device scratch (no allocations allowed)
__device__ float g_cs [kB*kChunks*kC*kD];  // chunk class sums -> exclusive prefix after scan
__device__ float g_tot[kB*kC*kD];          // per-batch class totals
__device__ float g_R  [kB*kC*kD];          // R[b][a][d] = sum_c P[c][a]*tot[b][c][d]
__device__ int   g_cls[kB*kL];
__device__ unsigned g_cnt[kB];             // scan arrival counters (self-resetting)
__device__ ull  g_Q2g [kC*kQP];            // dup(P[a][c]-P[c][a]), padded rows (built by sum CTA00)
__device__ ull  g_coefg[kC];               // dup((a!=0)-P[a][a])

// ---- packed f32x2 helpers ---------------------------------------------------
static __device__ __forceinline__ ull fadd2(ull a, ull b){
    ull r; asm("add.rn.f32x2 %0,%1,%2;" : "=l"(r) : "l"(a), "l"(b)); return r;
}
static __device__ __forceinline__ ull ffma2x(ull a, ull b, ull c){
    ull r; asm("fma.rn.f32x2 %0,%1,%2,%3;" : "=l"(r) : "l"(a), "l"(b), "l"(c)); return r;
}
static __device__ __forceinline__ ull dup2(float x){
    ull r; asm("mov.b64 %0,{%1,%1};" : "=l"(r) : "f"(x)); return r;
}
static __device__ __forceinline__ ull ldcg64(const float* p){
    ull r; asm volatile("ld.global.cg.b64 %0,[%1];" : "=l"(r) : "l"(p)); return r;
}
static __device__ __forceinline__ void stcg64(float* p, ull v){
    asm volatile("st.global.cg.b64 [%0],%1;" :: "l"(p), "l"(v));
}

// ===========================================================================
// K1: per-chunk class sums + idx detect/convert. Single accumulator bank
// (the 2nd bank's ~60 instr/thread cost exceeded its chain-shortening value).
// CTA (0,0) additionally materializes the Q/coef tables to global (hidden
// under the 1216-CTA wave); main_kernel then just copies them to smem.
__global__ void __launch_bounds__(kT) sum_kernel(const float* __restrict__ P,
                                                 const float* __restrict__ src,
                                                 const void*  __restrict__ cls)
{
    const int t = threadIdx.x;
    const int lane = t & 31, wid = t >> 5;
    const int chunk = blockIdx.x, b = blockIdx.y;
    const int posBase = b*kL + chunk*kCL;

    __shared__ ull acc[kC*kT];     // [class][thread] thread-private columns
    __shared__ int clsW[2*kCL];    // per-warp class lists

    // src loads first (MLP=19)
    const ull* sp = (const ull*)src + (size_t)posBase*kD2 + t;
    ull s[kCL];
    #pragma unroll
    for (int i = 0; i < kCL; i++) s[i] = sp[(size_t)i*kD2];

    // per-warp dtype detection: 32 probe words; >20 impossible under int64
    ull probe = ((const ull*)cls)[lane + wid*32];
    int is32 = __any_sync(0xffffffffu, probe > 20ULL);

    #pragma unroll
    for (int c = 0; c < kC; c++) acc[c*kT + t] = 0ULL;

    if (lane < kCL){
        int v = is32 ? ((const int*)cls)[posBase + lane]
                     : (int)((const long long*)cls)[posBase + lane];
        clsW[wid*kCL + lane] = v;
        if (wid == 0) g_cls[posBase + lane] = v;
    }
    __syncwarp();
    const int* myCls = clsW + wid*kCL;

    #pragma unroll
    for (int i = 0; i < kCL; i++){
        int c = myCls[i];                            // warp-uniform
        acc[c*kT + t] = fadd2(acc[c*kT + t], s[i]);  // private slot
    }

    float* cs = g_cs + ((size_t)(b*kChunks + chunk)*kC)*kD + 2*t;
    #pragma unroll
    for (int c = 0; c < kC; c++)
        stcg64(cs + (size_t)c*kD, acc[c*kT + t]);

    // ---- CTA (0,0): build global Q/coef tables (padded layout) ----
    if (chunk == 0 && b == 0){
        for (int idx = t; idx < kC*kQP; idx += kT){
            int a = idx / kQP, c = idx - a*kQP;
            g_Q2g[idx] = (c < kC) ? dup2(P[a*kC + c] - P[c*kC + a]) : 0ULL;
        }
        if (t < kC) g_coefg[t] = dup2((t != 0 ? 1.0f : 0.0f) - P[t*kC + t]);
    }
}

// ===========================================================================
// K2: CTAs [0,336): exclusive scan over 76 chunks per (b,c); last-arriving
//     CTA per batch computes R.  CTAs [336,1552): source->outS copy.
__global__ void __launch_bounds__(kT) scan_kernel(const float* __restrict__ P,
                                                  const float* __restrict__ src,
                                                  float* __restrict__ outS)
{
    const int t = threadIdx.x;
    const int bid = blockIdx.x;

    if (bid >= kScanCTAs){
        // ---- copy lane: outS = src for one chunk (9728B contiguous) ----
        if (outS){
            const int id = bid - kScanCTAs;           // 0..1215
            const size_t off = (size_t)id * (kCL*kD2) + t;
            const ull* sp = (const ull*)src + off;
            ull* op = (ull*)outS + off;
            ull v[kCL];
            #pragma unroll
            for (int i = 0; i < kCL; i++) v[i] = sp[(size_t)i*kD2];
            #pragma unroll
            for (int i = 0; i < kCL; i++) op[(size_t)i*kD2] = v[i];
        }
        return;
    }

    const int b = bid / kC, c = bid % kC;

    float* base = g_cs + ((size_t)b*kChunks*kC + c)*kD + 2*t;
    const size_t stride = (size_t)kC*kD;

    ull run = 0ULL;
    #pragma unroll
    for (int w = 0; w < kWaves; w++){
        ull v[kCL];
        #pragma unroll
        for (int k = 0; k < kCL; k++) v[k] = ldcg64(base + (size_t)(w*kCL + k)*stride);
        #pragma unroll
        for (int k = 0; k < kCL; k++){
            stcg64(base + (size_t)(w*kCL + k)*stride, run);
            run = fadd2(run, v[k]);
        }
    }
    stcg64(g_tot + ((size_t)b*kC + c)*kD + 2*t, run);

    __threadfence();
    __shared__ int isLast;
    if (t == 0){
        unsigned old = atomicAdd(&g_cnt[b], 1u);
        isLast = (old == (unsigned)(kC - 1));
    }
    __syncthreads();

    if (isLast){
        __threadfence();
        __shared__ float Psh[kC*kC];
        for (int i = t; i < kC*kC; i += kT) Psh[i] = P[i];

        ull tot2[kC];
        #pragma unroll
        for (int cc = 0; cc < kC; cc++)
            tot2[cc] = ldcg64(g_tot + ((size_t)b*kC + cc)*kD + 2*t);
        __syncthreads();

        #pragma unroll
        for (int a = 0; a < kC; a++){
            ull r0 = 0ULL, r1 = 0ULL, r2 = 0ULL;
            #pragma unroll
            for (int cc = 0; cc < 21; cc += 3){
                r0 = ffma2x(dup2(Psh[(cc+0)*kC + a]), tot2[cc+0], r0);
                r1 = ffma2x(dup2(Psh[(cc+1)*kC + a]), tot2[cc+1], r1);
                r2 = ffma2x(dup2(Psh[(cc+2)*kC + a]), tot2[cc+2], r2);
            }
            stcg64(g_R + ((size_t)b*kC + a)*kD + 2*t, fadd2(fadd2(r0, r1), r2));
        }
        if (t == 0) g_cnt[b] = 0u;            // self-reset for graph replay
    }
}

// ===========================================================================
// K3: fused[i] = QB[c_i] + coef[c_i]*s_i + sum_{j<i} M[i][j]*s_j
//     QB[a] = R[a] + sum_c Q[a,c]*base[c]  (present classes only)
__global__ void __launch_bounds__(kT) main_kernel(const float* __restrict__ src,
                                                  float* __restrict__ outF)
{
    __shared__ ull Q2[kC*kQP];       // dup(P[a][c]-P[c][a])
    __shared__ ull coef2[kC];
    __shared__ ull M2[kTRI];
    __shared__ ull QBs[kC*kT];       // per-class combined vector (thread columns)
    __shared__ int clsS[kCL];
    __shared__ int presentS[kC + 1];

    const int t = threadIdx.x;
    const int chunk = blockIdx.x, b = blockIdx.y;
    const int posBase = b*kL + chunk*kCL;

    // ---- independent loads first ----
    const ull* sp = (const ull*)src + (size_t)posBase*kD2 + t;
    ull s[kCL];
    #pragma unroll
    for (int i = 0; i < kCL; i++) s[i] = sp[(size_t)i*kD2];

    if (t < kCL) clsS[t] = g_cls[posBase + t];

    // Q/coef smem tables: straight copy from global (no div/mod, no FSUB/dup)
    #pragma unroll
    for (int idx = t; idx < kC*kQP; idx += kT) Q2[idx] = g_Q2g[idx];
    if (t < kC) coef2[t] = g_coefg[t];
    __syncthreads();

    // triangle coeffs M2[tri(i)+j] = Q[c_i, c_j], j<i
    // index from closed form; +-1 guard makes MUFU rounding irrelevant
    for (int idx = t; idx < kTRI; idx += kT){
        float f = sqrtf(8.0f*(float)idx + 1.0f);
        int i = (int)(0.5f*(1.0f + f));
        int tb = (i*(i-1)) >> 1;
        if (idx < tb){ i--; tb -= i; }
        else if (idx >= tb + i){ tb += i; i++; }
        M2[idx] = Q2[clsS[i]*kQP + clsS[idx - tb]];
    }

    if (t == 0){
        unsigned mask = 0;
        #pragma unroll
        for (int i = 0; i < kCL; i++) mask |= 1u << clsS[i];
        int n = 0;
        while (mask){ int a = __ffs(mask) - 1; mask &= mask - 1; presentS[1 + n++] = a; }
        presentS[0] = n;
    }

    // R preload (MLP over 21)
    const float* Rr = g_R + ((size_t)b*kC)*kD + 2*t;
    #pragma unroll
    for (int a = 0; a < kC; a++) QBs[a*kT + t] = ldcg64(Rr + (size_t)a*kD);

    // base = exclusive chunk-start class sums
    ull base[kC];
    {
        const float* cs = g_cs + ((size_t)(b*kChunks + chunk)*kC)*kD + 2*t;
        #pragma unroll
        for (int c = 0; c < kC; c++) base[c] = ldcg64(cs + (size_t)c*kD);
    }
    __syncthreads();

    // QB[a] for present classes only — 3-way split accumulators
    const int nd = presentS[0];
    for (int k = 0; k < nd; k++){
        int a = presentS[1 + k];             // warp-uniform
        const ull* qrow = Q2 + (size_t)a*kQP;
        ull r0 = QBs[a*kT + t], r1 = 0ULL, r2 = 0ULL;
        #pragma unroll
        for (int c = 0; c < 21; c += 3){
            r0 = ffma2x(qrow[c+0], base[c+0], r0);
            r1 = ffma2x(qrow[c+1], base[c+1], r1);
            r2 = ffma2x(qrow[c+2], base[c+2], r2);
        }
        QBs[a*kT + t] = fadd2(fadd2(r0, r1), r2);   // own column, no sync
    }

    ull* fp = (ull*)outF + (size_t)posBase*kD2 + t;

    #pragma unroll
    for (int i = 0; i < kCL; i++){
        int c = clsS[i];                     // warp-uniform
        const int tb = i*(i-1)/2;

        ull a0 = QBs[c*kT + t];
        ull a1 = ffma2x(coef2[c], s[i], 0ULL);
        ull a2 = 0ULL;

        // strict-lower triangle dot, 3 independent streams
        int j = 0;
        #pragma unroll
        for (; j + 2 < i; j += 3){
            a0 = ffma2x(M2[tb + j + 0], s[j + 0], a0);
            a1 = ffma2x(M2[tb + j + 1], s[j + 1], a1);
            a2 = ffma2x(M2[tb + j + 2], s[j + 2], a2);
        }
        #pragma unroll
        for (; j < i; j++)
            a0 = ffma2x(M2[tb + j], s[j], a0);

        fp[(size_t)i*kD2] = fadd2(fadd2(a0, a1), a2);
    }
}

// ===========================================================================
extern "C" void kernel_launch(void* const* d_in, const int* in_sizes, int n_in,
                              void* d_out, int out_size)
{
    const float* P   = (const float*)d_in[0];  // cls_r_prob [C,C]
    const float* src = (const float*)d_in[1];  // source [B,L,D]
    const void*  cls = d_in[2];                // class_idx [B,L]

    float* outF = (float*)d_out;
    const long long fusedElems = (long long)kB*kL*kD;
    float* outS = ((long long)out_size >= 2*fusedElems) ? (outF + fusedElems) : nullptr;

    sum_kernel <<<dim3(kChunks, kB), kT>>>(P, src, cls);
    scan_kernel<<<kScanCTAs + kCopyCTAs, kT>>>(P, src, outS);
    main_kernel<<<dim3(kChunks, kB), kT>>>(src, outF);
}

// round 16
// speedup vs baseline: 1.4640x; 1.4640x over previous
#include <cuda_runtime.h>

#define kB 16
#define kL 1444
#define kD 128
#define kD2 64          // float2 lanes per position
#define kC 21
#define kChunks 76
#define kCL 19          // 76*19 == 1444
#define kT 64
#define kQP 22          // padded Q row stride
#define kWaves 4        // 76 = 4*19 scan waves
#define kTRI 171        // 19*18/2
#define kScanCTAs (kB*kC)          // 336
#define kCopyCTAs (kB*kChunks)     // 1216

typedef unsigned long long ull;

// Device scratch (no allocations allowed)
__device__ float g_cs [kB*kChunks*kC*kD];  // chunk class sums -> exclusive prefix after scan
__device__ float g_tot[kB*kC*kD];          // per-batch class totals
__device__ float g_R  [kB*kC*kD];          // R[b][a][d] = sum_c P[c][a]*tot[b][c][d]
__device__ int   g_cls[kB*kL];
__device__ unsigned g_cnt[kB];             // scan arrival counters (self-resetting)
__device__ ull  g_Q2g [kC*kQP];            // dup(P[a][c]-P[c][a]) padded (built in scan launch)
__device__ ull  g_coefg[kC];               // dup((a!=0)-P[a][a])

// ---- packed f32x2 helpers ---------------------------------------------------
static __device__ __forceinline__ ull fadd2(ull a, ull b){
    ull r; asm("add.rn.f32x2 %0,%1,%2;" : "=l"(r) : "l"(a), "l"(b)); return r;
}
static __device__ __forceinline__ ull ffma2x(ull a, ull b, ull c){
    ull r; asm("fma.rn.f32x2 %0,%1,%2,%3;" : "=l"(r) : "l"(a), "l"(b), "l"(c)); return r;
}
static __device__ __forceinline__ ull dup2(float x){
    ull r; asm("mov.b64 %0,{%1,%1};" : "=l"(r) : "f"(x)); return r;
}
static __device__ __forceinline__ ull ldcg64(const float* p){
    ull r; asm volatile("ld.global.cg.b64 %0,[%1];" : "=l"(r) : "l"(p)); return r;
}
static __device__ __forceinline__ void stcg64(float* p, ull v){
    asm volatile("st.global.cg.b64 [%0],%1;" :: "l"(p), "l"(v));
}

// ===========================================================================
// K1: per-chunk class sums + idx detect/convert. EXACT round-12 body —
// two accumulator banks keep 19 s[] values live (regs=70) which is what
// preserves the front-batched MLP=19 load schedule. Do not touch.
__global__ void __launch_bounds__(kT) sum_kernel(const float* __restrict__ src,
                                                 const void*  __restrict__ cls)
{
    const int t = threadIdx.x;
    const int lane = t & 31, wid = t >> 5;
    const int chunk = blockIdx.x, b = blockIdx.y;
    const int posBase = b*kL + chunk*kCL;

    __shared__ ull acc0[kC*kT];    // even-i bank
    __shared__ ull acc1[kC*kT];    // odd-i bank
    __shared__ int clsW[2*kCL];    // per-warp class lists

    // src loads first (MLP=19)
    const ull* sp = (const ull*)src + (size_t)posBase*kD2 + t;
    ull s[kCL];
    #pragma unroll
    for (int i = 0; i < kCL; i++) s[i] = sp[(size_t)i*kD2];

    // per-warp dtype detection: 32 probe words; >20 impossible under int64
    ull probe = ((const ull*)cls)[lane + wid*32];
    int is32 = __any_sync(0xffffffffu, probe > 20ULL);

    #pragma unroll
    for (int c = 0; c < kC; c++){ acc0[c*kT + t] = 0ULL; acc1[c*kT + t] = 0ULL; }

    if (lane < kCL){
        int v = is32 ? ((const int*)cls)[posBase + lane]
                     : (int)((const long long*)cls)[posBase + lane];
        clsW[wid*kCL + lane] = v;
        if (wid == 0) g_cls[posBase + lane] = v;
    }
    __syncwarp();
    const int* myCls = clsW + wid*kCL;

    #pragma unroll
    for (int i = 0; i < kCL; i += 2){
        int c = myCls[i];                                // warp-uniform
        acc0[c*kT + t] = fadd2(acc0[c*kT + t], s[i]);
        if (i + 1 < kCL){
            int c1 = myCls[i + 1];
            acc1[c1*kT + t] = fadd2(acc1[c1*kT + t], s[i + 1]);
        }
    }

    float* cs = g_cs + ((size_t)(b*kChunks + chunk)*kC)*kD + 2*t;
    #pragma unroll
    for (int c = 0; c < kC; c++)
        stcg64(cs + (size_t)c*kD, fadd2(acc0[c*kT + t], acc1[c*kT + t]));
}

// ===========================================================================
// K2: CTAs [0,336): exclusive scan over 76 chunks per (b,c); last-arriving
//     CTA per batch computes R.  CTAs [336,1552): source->outS copy; copy
//     CTA #0 additionally builds the global Q/coef tables for main_kernel.
__global__ void __launch_bounds__(kT) scan_kernel(const float* __restrict__ P,
                                                  const float* __restrict__ src,
                                                  float* __restrict__ outS)
{
    const int t = threadIdx.x;
    const int bid = blockIdx.x;

    if (bid >= kScanCTAs){
        const int id = bid - kScanCTAs;               // 0..1215

        // copy CTA #0 builds the dup'd Q/coef tables (visible to main_kernel
        // via stream ordering of the next launch)
        if (id == 0){
            for (int idx = t; idx < kC*kQP; idx += kT){
                int a = idx / kQP, c = idx - a*kQP;
                g_Q2g[idx] = (c < kC) ? dup2(P[a*kC + c] - P[c*kC + a]) : 0ULL;
            }
            if (t < kC) g_coefg[t] = dup2((t != 0 ? 1.0f : 0.0f) - P[t*kC + t]);
        }

        // ---- copy lane: outS = src for one chunk (9728B contiguous) ----
        if (outS){
            const size_t off = (size_t)id * (kCL*kD2) + t;
            const ull* sp = (const ull*)src + off;
            ull* op = (ull*)outS + off;
            ull v[kCL];
            #pragma unroll
            for (int i = 0; i < kCL; i++) v[i] = sp[(size_t)i*kD2];
            #pragma unroll
            for (int i = 0; i < kCL; i++) op[(size_t)i*kD2] = v[i];
        }
        return;
    }

    const int b = bid / kC, c = bid % kC;

    float* base = g_cs + ((size_t)b*kChunks*kC + c)*kD + 2*t;
    const size_t stride = (size_t)kC*kD;

    ull run = 0ULL;
    #pragma unroll
    for (int w = 0; w < kWaves; w++){
        ull v[kCL];
        #pragma unroll
        for (int k = 0; k < kCL; k++) v[k] = ldcg64(base + (size_t)(w*kCL + k)*stride);
        #pragma unroll
        for (int k = 0; k < kCL; k++){
            stcg64(base + (size_t)(w*kCL + k)*stride, run);
            run = fadd2(run, v[k]);
        }
    }
    stcg64(g_tot + ((size_t)b*kC + c)*kD + 2*t, run);

    __threadfence();
    __shared__ int isLast;
    if (t == 0){
        unsigned old = atomicAdd(&g_cnt[b], 1u);
        isLast = (old == (unsigned)(kC - 1));
    }
    __syncthreads();

    if (isLast){
        __threadfence();
        __shared__ float Psh[kC*kC];
        for (int i = t; i < kC*kC; i += kT) Psh[i] = P[i];

        ull tot2[kC];
        #pragma unroll
        for (int cc = 0; cc < kC; cc++)
            tot2[cc] = ldcg64(g_tot + ((size_t)b*kC + cc)*kD + 2*t);
        __syncthreads();

        #pragma unroll
        for (int a = 0; a < kC; a++){
            ull r0 = 0ULL, r1 = 0ULL, r2 = 0ULL;
            #pragma unroll
            for (int cc = 0; cc < 21; cc += 3){
                r0 = ffma2x(dup2(Psh[(cc+0)*kC + a]), tot2[cc+0], r0);
                r1 = ffma2x(dup2(Psh[(cc+1)*kC + a]), tot2[cc+1], r1);
                r2 = ffma2x(dup2(Psh[(cc+2)*kC + a]), tot2[cc+2], r2);
            }
            stcg64(g_R + ((size_t)b*kC + a)*kD + 2*t, fadd2(fadd2(r0, r1), r2));
        }
        if (t == 0) g_cnt[b] = 0u;            // self-reset for graph replay
    }
}

// ===========================================================================
// K3: fused[i] = QB[c_i] + coef[c_i]*s_i + sum_{j<i} M[i][j]*s_j
//     QB[a] = R[a] + sum_c Q[a,c]*base[c]  (present classes only)
__global__ void __launch_bounds__(kT) main_kernel(const float* __restrict__ src,
                                                  float* __restrict__ outF)
{
    __shared__ ull Q2[kC*kQP];       // dup(P[a][c]-P[c][a])
    __shared__ ull coef2[kC];
    __shared__ ull M2[kTRI];
    __shared__ ull QBs[kC*kT];       // per-class combined vector (thread columns)
    __shared__ int clsS[kCL];
    __shared__ int presentS[kC + 1];

    const int t = threadIdx.x;
    const int chunk = blockIdx.x, b = blockIdx.y;
    const int posBase = b*kL + chunk*kCL;

    // ---- independent loads first ----
    const ull* sp = (const ull*)src + (size_t)posBase*kD2 + t;
    ull s[kCL];
    #pragma unroll
    for (int i = 0; i < kCL; i++) s[i] = sp[(size_t)i*kD2];

    if (t < kCL) clsS[t] = g_cls[posBase + t];

    // Q/coef smem tables: straight copy from global (no div/mod, no FSUB/dup)
    #pragma unroll
    for (int idx = t; idx < kC*kQP; idx += kT) Q2[idx] = g_Q2g[idx];
    if (t < kC) coef2[t] = g_coefg[t];
    __syncthreads();

    // triangle coeffs M2[tri(i)+j] = Q[c_i, c_j], j<i
    // index from closed form; +-1 guard makes MUFU rounding irrelevant
    for (int idx = t; idx < kTRI; idx += kT){
        float f = sqrtf(8.0f*(float)idx + 1.0f);
        int i = (int)(0.5f*(1.0f + f));
        int tb = (i*(i-1)) >> 1;
        if (idx < tb){ i--; tb -= i; }
        else if (idx >= tb + i){ tb += i; i++; }
        M2[idx] = Q2[clsS[i]*kQP + clsS[idx - tb]];
    }

    if (t == 0){
        unsigned mask = 0;
        #pragma unroll
        for (int i = 0; i < kCL; i++) mask |= 1u << clsS[i];
        int n = 0;
        while (mask){ int a = __ffs(mask) - 1; mask &= mask - 1; presentS[1 + n++] = a; }
        presentS[0] = n;
    }

    // R preload (MLP over 21)
    const float* Rr = g_R + ((size_t)b*kC)*kD + 2*t;
    #pragma unroll
    for (int a = 0; a < kC; a++) QBs[a*kT + t] = ldcg64(Rr + (size_t)a*kD);

    // base = exclusive chunk-start class sums
    ull base[kC];
    {
        const float* cs = g_cs + ((size_t)(b*kChunks + chunk)*kC)*kD + 2*t;
        #pragma unroll
        for (int c = 0; c < kC; c++) base[c] = ldcg64(cs + (size_t)c*kD);
    }
    __syncthreads();

    // QB[a] for present classes only — 3-way split accumulators
    const int nd = presentS[0];
    for (int k = 0; k < nd; k++){
        int a = presentS[1 + k];             // warp-uniform
        const ull* qrow = Q2 + (size_t)a*kQP;
        ull r0 = QBs[a*kT + t], r1 = 0ULL, r2 = 0ULL;
        #pragma unroll
        for (int c = 0; c < 21; c += 3){
            r0 = ffma2x(qrow[c+0], base[c+0], r0);
            r1 = ffma2x(qrow[c+1], base[c+1], r1);
            r2 = ffma2x(qrow[c+2], base[c+2], r2);
        }
        QBs[a*kT + t] = fadd2(fadd2(r0, r1), r2);   // own column, no sync
    }

    ull* fp = (ull*)outF + (size_t)posBase*kD2 + t;

    #pragma unroll
    for (int i = 0; i < kCL; i++){
        int c = clsS[i];                     // warp-uniform
        const int tb = i*(i-1)/2;

        ull a0 = QBs[c*kT + t];
        ull a1 = ffma2x(coef2[c], s[i], 0ULL);
        ull a2 = 0ULL;

        // strict-lower triangle dot, 3 independent streams
        int j = 0;
        #pragma unroll
        for (; j + 2 < i; j += 3){
            a0 = ffma2x(M2[tb + j + 0], s[j + 0], a0);
            a1 = ffma2x(M2[tb + j + 1], s[j + 1], a1);
            a2 = ffma2x(M2[tb + j + 2], s[j + 2], a2);
        }
        #pragma unroll
        for (; j < i; j++)
            a0 = ffma2x(M2[tb + j], s[j], a0);

        fp[(size_t)i*kD2] = fadd2(fadd2(a0, a1), a2);
    }
}

// ===========================================================================
extern "C" void kernel_launch(void* const* d_in, const int* in_sizes, int n_in,
                              void* d_out, int out_size)
{
    const float* P   = (const float*)d_in[0];  // cls_r_prob [C,C]
    const float* src = (const float*)d_in[1];  // source [B,L,D]
    const void*  cls = d_in[2];                // class_idx [B,L]

    float* outF = (float*)d_out;
    const long long fusedElems = (long long)kB*kL*kD;
    float* outS = ((long long)out_size >= 2*fusedElems) ? (outF + fusedElems) : nullptr;

    sum_kernel <<<dim3(kChunks, kB), kT>>>(src, cls);
    scan_kernel<<<kScanCTAs + kCopyCTAs, kT>>>(P, src, outS);
    main_kernel<<<dim3(kChunks, kB), kT>>>(src, outF);
}